// round 11
// baseline (speedup 1.0000x reference)
#include <cuda_runtime.h>
#include <cstdint>

// SINDy library: out[row] = [1, z(32), z_i*z_j (528), z_a*z_b*z_c (5984), sin(z)(32)]
// 8192 rows x 6577 cols fp32.
// R11 = R10 (4-wide branchless groups, fixup-redirect, one LDS.128 + one STG.128
// per thread-iter) + TWO rows per block built in one shared prologue:
// rows bid and bid+4096 (same phase), z loads concurrent, shared barriers.

#define NDIM     32
#define NPAIRS   528
#define NCOLS    6577
#define SBUF_PAD 600
#define NTHREADS 256
#define RPB      2
#define GRID     4096                 // 8192 / RPB; 4096 % 4 == 0 -> same phase
#define FIXBASE  (4 * SBUF_PAD)       // float idx of fixup region; 9600 B -> 16B aligned
#define FIX_MAX  320                  // >= 4 * (#boundary groups per phase)
#define SALL_N   (FIXBASE + FIX_MAX)
#define TB_PAD   1920                 // >= max ng4 (1644) + NTHREADS

static constexpr int pair_index(int i, int j) {
    return i * NDIM - (i * (i - 1)) / 2 + (j - i);
}

// ---- per-column (k, a): value = s_mul[a] * buf[k]; a=32 -> 1.0 ----
struct ColTbl { unsigned short e[NCOLS]; };
static constexpr ColTbl make_col_tbl() {
    ColTbl t{};
    for (int c = 0; c < 561; ++c)
        t.e[c] = (unsigned short)((unsigned)c | (32u << 10));
    {
        int col = 561;
        for (int a = 0; a < NDIM; ++a)
            for (int b = a; b < NDIM; ++b)
                for (int c = b; c < NDIM; ++c) {
                    unsigned k = 33u + (unsigned)pair_index(b, c);
                    t.e[col++] = (unsigned short)(k | ((unsigned)a << 10));
                }
    }
    for (int i = 0; i < NDIM; ++i)
        t.e[6545 + i] = (unsigned short)((unsigned)(561 + i) | (32u << 10));
    return t;
}
__device__ constexpr ColTbl G_COL = make_col_tbl();

// ---- per-column decomposition into s_m3[65] = [z(32), 1.0, sin(32)] ----
static constexpr unsigned col_m3(int c) {
    if (c == 0)   return 32u | (32u << 7) | (32u << 14);
    if (c < 33)   return (unsigned)(c - 1) | (32u << 7) | (32u << 14);
    if (c < 561) {
        int p = c - 33, i = 0;
        while (p >= NDIM - i) { p -= NDIM - i; ++i; }
        return (unsigned)i | ((unsigned)(i + p) << 7) | (32u << 14);
    }
    if (c < 6545) {
        int r = c - 561, a = 0;
        while (true) {
            int m = NDIM - a, cnt = m * (m + 1) / 2;
            if (r < cnt) break;
            r -= cnt; ++a;
        }
        int b = a;
        while (r >= NDIM - b) { r -= NDIM - b; ++b; }
        return (unsigned)a | ((unsigned)b << 7) | ((unsigned)(b + r) << 14);
    }
    return (unsigned)(33 + (c - 6545)) | (32u << 7) | (32u << 14);
}

// ---- 4-wide group table with fixup redirection, per phase ----
struct Tbl4 {
    unsigned e[4][TB_PAD];        // low16: byte off into s_all; [16..30): za byte off
    unsigned fixsrc[4][FIX_MAX];
    int      ng[4];
    int      nfix[4];
};

static constexpr Tbl4 make_tbl4() {
    ColTbl ct = make_col_tbl();
    Tbl4 t{};
    for (int ph = 0; ph < 4; ++ph) {
        int ng = (NCOLS - ph) / 4;
        t.ng[ph] = ng;
        int nf = 0;
        for (int g = 0; g < ng; ++g) {
            int c0 = ph + 4 * g;
            unsigned k0 = ct.e[c0] & 1023u;
            unsigned a0 = (unsigned)(ct.e[c0] >> 10);
            bool uniform = true;
            for (int j = 1; j < 4; ++j) {
                unsigned kj = ct.e[c0 + j] & 1023u;
                unsigned aj = (unsigned)(ct.e[c0 + j] >> 10);
                if (kj != k0 + (unsigned)j || aj != a0) { uniform = false; break; }
            }
            if (uniform) {
                unsigned P   = (4u - (k0 & 3u)) & 3u;
                unsigned off = (P * SBUF_PAD + k0 + P) * 4u;
                t.e[ph][g] = off | ((a0 * 4u) << 16);
            } else {
                unsigned off = (unsigned)(FIXBASE + nf) * 4u;
                t.e[ph][g] = off | ((32u * 4u) << 16);
                for (int j = 0; j < 4; ++j)
                    t.fixsrc[ph][nf++] = col_m3(c0 + j);
            }
        }
        t.nfix[ph] = nf;
        for (int g = ng; g < TB_PAD; ++g) t.e[ph][g] = 0;
        for (int i = nf; i < FIX_MAX; ++i) t.fixsrc[ph][i] = 32u | (32u << 7) | (32u << 14);
    }
    return t;
}
__device__ constexpr Tbl4 G4 = make_tbl4();

struct PairTbl { unsigned short e[NPAIRS]; };
static constexpr PairTbl make_pair_tbl() {
    PairTbl t{};
    int p = 0;
    for (int i = 0; i < NDIM; ++i)
        for (int j = i; j < NDIM; ++j)
            t.e[p++] = (unsigned short)((unsigned)i | ((unsigned)j << 8));
    return t;
}
__device__ constexpr PairTbl G_PAIR = make_pair_tbl();

__global__ __launch_bounds__(NTHREADS) void sindy_library_kernel(
    const float* __restrict__ z, float* __restrict__ out)
{
    // Per row: 4 shifted buf copies + fixup region (s_all), z/1.0 multipliers.
    __shared__ __align__(16) float s_all[RPB][SALL_N];
    __shared__ float s_mul[RPB][NDIM + 1];
    __shared__ float s_m3[RPB][65];

    const int bid = blockIdx.x;
    const int t   = threadIdx.x;
    const int ph  = (4 - (bid & 3)) & 3;   // same for both rows

    // ---- shared prologue: both rows' z loads issue concurrently ----
    if (t < RPB * NDIM) {
        int r = t >> 5, i = t & 31;
        float v  = z[(bid + r * GRID) * NDIM + i];
        float sv = __sinf(v);
        s_mul[r][i]    = v;
        s_m3[r][i]     = v;
        s_m3[r][33 + i] = sv;
        #pragma unroll
        for (int P = 0; P < 4; ++P) {
            s_all[r][P * SBUF_PAD + P + 1 + i]   = v;
            s_all[r][P * SBUF_PAD + P + 561 + i] = sv;
        }
    } else if (t < RPB * NDIM + RPB) {
        int r = t - RPB * NDIM;
        s_mul[r][NDIM] = 1.0f;
        s_m3[r][32]    = 1.0f;
        #pragma unroll
        for (int P = 0; P < 4; ++P) s_all[r][P * SBUF_PAD + P] = 1.0f;
    }
    __syncthreads();

    // Pair products for both rows into all 4 shifted copies.
    for (int p = t; p < NPAIRS; p += NTHREADS) {
        unsigned ij = (unsigned)G_PAIR.e[p];
        unsigned i = ij & 31u, j = (ij >> 8) & 31u;
        #pragma unroll
        for (int r = 0; r < RPB; ++r) {
            float v = s_mul[r][i] * s_mul[r][j];
            #pragma unroll
            for (int P = 0; P < 4; ++P) s_all[r][P * SBUF_PAD + P + 33 + p] = v;
        }
    }
    // Fixup values for both rows (pre-multiplied; za = 1.0 in main loop).
    {
        const int nfix = G4.nfix[ph];
        for (int f = t; f < nfix; f += NTHREADS) {
            unsigned s = __ldg(&G4.fixsrc[ph][f]);
            unsigned m0 = s & 127u, m1 = (s >> 7) & 127u, m2 = (s >> 14) & 127u;
            #pragma unroll
            for (int r = 0; r < RPB; ++r)
                s_all[r][FIXBASE + f] = s_m3[r][m0] * s_m3[r][m1] * s_m3[r][m2];
        }
    }
    __syncthreads();

    const int ng = G4.ng[ph];
    const unsigned* __restrict__ tb = &G4.e[ph][0];

    // ---- main loops: outer row loop keeps ONE LDS.128 + ONE STG.128 per iter ----
    #pragma unroll
    for (int r = 0; r < RPB; ++r) {
        float* __restrict__ o = out + (size_t)(bid + r * GRID) * NCOLS;
        const char* __restrict__ sc = (const char*)&s_all[r][0];
        const char* __restrict__ sm = (const char*)&s_mul[r][0];

        if (t < ph) {
            unsigned e = (unsigned)G_COL.e[t];
            o[t] = s_mul[r][e >> 10] * s_all[r][e & 1023u];
        }

        unsigned e = __ldg(&tb[t]);
        for (int g = t; g < ng; g += NTHREADS) {
            unsigned en = __ldg(&tb[g + NTHREADS]);   // padded: always in-bounds

            float4 b  = *(const float4*)(sc + (e & 0xFFFFu));
            float  za = *(const float*)(sm + (e >> 16));
            float4 rr = make_float4(za * b.x, za * b.y, za * b.z, za * b.w);

            __stcs((float4*)(o + ph + 4 * g), rr);
            e = en;
        }

        {
            int c = ph + 4 * ng + t;
            if (c < NCOLS) {
                unsigned ee = (unsigned)G_COL.e[c];
                o[c] = s_mul[r][ee >> 10] * s_all[r][ee & 1023u];
            }
        }
    }
}

extern "C" void kernel_launch(void* const* d_in, const int* in_sizes, int n_in,
                              void* d_out, int out_size) {
    const float* z   = (const float*)d_in[0];
    float*       out = (float*)d_out;
    sindy_library_kernel<<<GRID, NTHREADS>>>(z, out);
}